// round 8
// baseline (speedup 1.0000x reference)
#include <cuda_runtime.h>
#include <cuda_bf16.h>
#include <cstdint>
#include <math.h>

// ---------------- problem constants ----------------
#define NSEQ   512
#define LSEQ   64
#define MDIM   (NSEQ*LSEQ)  // 32768
#define CDIM   256
#define DI     512
#define NXZ    1024
#define DST    16
#define DTR    16
#define NXP    48

// ---------------- scratch (device symbols: referenced ONLY inside device code) ----------------
__device__ float g_xz [MDIM * NXZ];     // 134 MB
__device__ float g_xc [MDIM * DI];      // 67 MB
__device__ float g_dbc[MDIM * NXP];     // 6.3 MB
__device__ float g_tmp[MDIM * CDIM];    // 33.5 MB
__device__ float g_xT [8 * 256 * 64 * 64];
__device__ __nv_bfloat16 g_ah [MDIM * 256];
__device__ __nv_bfloat16 g_al [MDIM * 256];
__device__ __nv_bfloat16 g_yh [MDIM * DI];
__device__ __nv_bfloat16 g_yl [MDIM * DI];
__device__ __nv_bfloat16 g_wtih[1024 * 256];
__device__ __nv_bfloat16 g_wtil[1024 * 256];
__device__ __nv_bfloat16 g_wtoh[256 * 512];
__device__ __nv_bfloat16 g_wtol[256 * 512];

__device__ __forceinline__ float siluf(float v)    { return v / (1.f + __expf(-v)); }
__device__ __forceinline__ float softplusf(float v){ return (v > 20.f) ? v : log1pf(expf(v)); }

// ---------------- mma.sync / cp.async helpers ----------------
__device__ __forceinline__ void mma16816(float* c, const uint32_t* a, const uint32_t* b) {
    asm volatile(
        "mma.sync.aligned.m16n8k16.row.col.f32.bf16.bf16.f32 "
        "{%0,%1,%2,%3}, {%4,%5,%6,%7}, {%8,%9}, {%0,%1,%2,%3};\n"
        : "+f"(c[0]), "+f"(c[1]), "+f"(c[2]), "+f"(c[3])
        : "r"(a[0]), "r"(a[1]), "r"(a[2]), "r"(a[3]), "r"(b[0]), "r"(b[1]));
}
__device__ __forceinline__ void cp16(uint32_t saddr, const void* g) {
    asm volatile("cp.async.cg.shared.global [%0], [%1], 16;" :: "r"(saddr), "l"(g));
}
#define CP_COMMIT() asm volatile("cp.async.commit_group;" ::: "memory")
#define CP_WAIT(n)  asm volatile("cp.async.wait_group %0;" :: "n"(n) : "memory")

// ---------------- transpose x(b,c,h,w) -> xT(b,c,w,h) ----------------
__global__ void k_transpose_hw(const float* __restrict__ x) {
    __shared__ float tile[32][33];
    int bc = blockIdx.z, ht = blockIdx.y, wt = blockIdx.x;
    const float* src = x    + (size_t)bc * 4096;
    float*       dst = g_xT + (size_t)bc * 4096;
    int tx = threadIdx.x, ty = threadIdx.y;
    #pragma unroll
    for (int i = 0; i < 4; i++) {
        int h = ht * 32 + ty + i * 8;
        tile[ty + i * 8][tx] = src[h * 64 + wt * 32 + tx];
    }
    __syncthreads();
    #pragma unroll
    for (int i = 0; i < 4; i++) {
        int w = wt * 32 + ty + i * 8;
        dst[w * 64 + ht * 32 + tx] = tile[tx][ty + i * 8];
    }
}

// ---------------- convert A: src[(b*256+k)*4096+rem] -> bf16 hi/lo [m][k] ----------------
__global__ void k_convA(const float* __restrict__ xin, int useT) {
    __shared__ float t[32][33];
    const float* src = useT ? g_xT : xin;
    int b = blockIdx.z, kt = blockIdx.y, rt = blockIdx.x;
    int tx = threadIdx.x, ty = threadIdx.y;
    #pragma unroll
    for (int i = 0; i < 4; i++) {
        int k = kt * 32 + ty + i * 8;
        t[ty + i * 8][tx] = src[(size_t)(b * 256 + k) * 4096 + rt * 32 + tx];
    }
    __syncthreads();
    #pragma unroll
    for (int i = 0; i < 4; i++) {
        int rem = rt * 32 + ty + i * 8;
        size_t m = (size_t)b * 4096 + rem;
        float v = t[tx][ty + i * 8];
        __nv_bfloat16 h = __float2bfloat16(v);
        g_ah[m * 256 + kt * 32 + tx] = h;
        g_al[m * 256 + kt * 32 + tx] = __float2bfloat16(v - __bfloat162float(h));
    }
}

// ---------------- convert+transpose weights: W[R,C] fp32 -> T[C,R] bf16 hi/lo ----------------
__global__ void k_convW(const float* __restrict__ W, int R, int C, int which) {
    __shared__ float t[32][33];
    __nv_bfloat16* Th = which ? g_wtoh : g_wtih;
    __nv_bfloat16* Tl = which ? g_wtol : g_wtil;
    int r0 = blockIdx.y * 32, c0 = blockIdx.x * 32;
    int tx = threadIdx.x, ty = threadIdx.y;
    #pragma unroll
    for (int i = 0; i < 4; i++)
        t[ty + i * 8][tx] = W[(size_t)(r0 + ty + i * 8) * C + c0 + tx];
    __syncthreads();
    #pragma unroll
    for (int i = 0; i < 4; i++) {
        float v = t[tx][ty + i * 8];
        int oc = c0 + ty + i * 8;
        __nv_bfloat16 h = __float2bfloat16(v);
        Th[(size_t)oc * R + r0 + tx] = h;
        Tl[(size_t)oc * R + r0 + tx] = __float2bfloat16(v - __bfloat162float(h));
    }
}

// ---------------- shared GEMM config ----------------
// mode 0: A=g_ah/g_al [32768,256], B=g_wtih/g_wtil [1024,256], C=g_xz, ldc=1024
// mode 1: A=g_yh/g_yl [32768,512], B=g_wtoh/g_wtol [256,512],  C=g_tmp, ldc=256
__device__ __forceinline__ void gemm_cfg(int mode, const __nv_bfloat16*& Ah,
    const __nv_bfloat16*& Al, const __nv_bfloat16*& Bh, const __nv_bfloat16*& Bl,
    float*& Cout, int& K, int& ldc)
{
    if (mode == 0) { Ah = g_ah; Al = g_al; Bh = g_wtih; Bl = g_wtil; Cout = g_xz;  K = 256; ldc = NXZ; }
    else           { Ah = g_yh; Al = g_yl; Bh = g_wtoh; Bl = g_wtol; Cout = g_tmp; K = 512; ldc = CDIM; }
}

// ---------------- GEMM epilogue (shared) ----------------
__device__ __forceinline__ void gemm_epilogue(float acc[4][4][4], float* Cout, int ldc,
                                              int m0, int n0, int wr, int wc, int g, int tg)
{
    #pragma unroll
    for (int mt = 0; mt < 4; mt++)
        #pragma unroll
        for (int nt = 0; nt < 4; nt++) {
            int row = m0 + wr * 64 + mt * 16 + g;
            int col = n0 + wc * 32 + nt * 8 + tg * 2;
            *(float2*)&Cout[(size_t)row * ldc + col] =
                make_float2(acc[mt][nt][0], acc[mt][nt][1]);
            *(float2*)&Cout[(size_t)(row + 8) * ldc + col] =
                make_float2(acc[mt][nt][2], acc[mt][nt][3]);
        }
}

// ---------------- HMMA bf16x3 GEMM, BK=32, cp.async 2-stage, DYNAMIC smem ----------------
// SSTR32=40 (80B rows): frag LDS banks (20*g+tg)%32 all distinct.
// stage = 4 tiles x 128 x 40 x 2B = 40960 B; 2 stages = 81920 B dynamic.
#define SSTR32 40
#define TILE32 (128 * SSTR32)
#define STG32  (4 * TILE32)
__global__ void __launch_bounds__(256, 2) k_mma_gemm32(int mode) {
    extern __shared__ __nv_bfloat16 dsm[];

    const __nv_bfloat16 *Ah, *Al, *Bh, *Bl;
    float* Cout; int K, ldc;
    gemm_cfg(mode, Ah, Al, Bh, Bl, Cout, K, ldc);

    int tid = threadIdx.x, warp = tid >> 5, lane = tid & 31;
    int wr = warp >> 2, wc = warp & 3;
    int g = lane >> 2, tg = lane & 3;
    int m0 = blockIdx.y * 128, n0 = blockIdx.x * 128;

    const __nv_bfloat16* base0 = Ah + (size_t)m0 * K;
    const __nv_bfloat16* base1 = Al + (size_t)m0 * K;
    const __nv_bfloat16* base2 = Bh + (size_t)n0 * K;
    const __nv_bfloat16* base3 = Bl + (size_t)n0 * K;

    uint32_t sbase = (uint32_t)__cvta_generic_to_shared(dsm);
    // load slots: 128 rows x 4 x 16B chunks per tile, 2 per thread per tile
    float acc[4][4][4];
    #pragma unroll
    for (int i = 0; i < 4; i++)
        #pragma unroll
        for (int j = 0; j < 4; j++)
            #pragma unroll
            for (int q = 0; q < 4; q++) acc[i][j][q] = 0.f;

    // prologue: stage 0
    #pragma unroll
    for (int i = 0; i < 2; i++) {
        int idx = tid + i * 256;
        int r = idx >> 2, q = idx & 3;
        size_t go = (size_t)r * K + q * 8;
        uint32_t so = sbase + (uint32_t)(r * SSTR32 + q * 8) * 2;
        cp16(so + 0 * TILE32 * 2, base0 + go);
        cp16(so + 1 * TILE32 * 2, base1 + go);
        cp16(so + 2 * TILE32 * 2, base2 + go);
        cp16(so + 3 * TILE32 * 2, base3 + go);
    }
    CP_COMMIT();

    const int T = K >> 5;
    for (int it = 0; it < T; it++) {
        if (it + 1 < T) {
            int k0n = (it + 1) << 5;
            uint32_t sb = sbase + ((it + 1) & 1) * STG32 * 2;
            #pragma unroll
            for (int i = 0; i < 2; i++) {
                int idx = tid + i * 256;
                int r = idx >> 2, q = idx & 3;
                size_t go = (size_t)r * K + q * 8 + k0n;
                uint32_t so = sb + (uint32_t)(r * SSTR32 + q * 8) * 2;
                cp16(so + 0 * TILE32 * 2, base0 + go);
                cp16(so + 1 * TILE32 * 2, base1 + go);
                cp16(so + 2 * TILE32 * 2, base2 + go);
                cp16(so + 3 * TILE32 * 2, base3 + go);
            }
            CP_COMMIT();
            CP_WAIT(1);
        } else {
            CP_WAIT(0);
        }
        __syncthreads();

        const __nv_bfloat16* s0  = dsm + (it & 1) * STG32;
        const __nv_bfloat16* sAh = s0;
        const __nv_bfloat16* sAl = s0 + TILE32;
        const __nv_bfloat16* sBh = s0 + 2 * TILE32;
        const __nv_bfloat16* sBl = s0 + 3 * TILE32;

        #pragma unroll
        for (int ks = 0; ks < 2; ks++) {
            int kb = ks * 16 + tg * 2;
            uint32_t a_hi[4][4], a_lo[4][4], b_hi[4][2], b_lo[4][2];
            #pragma unroll
            for (int mt = 0; mt < 4; mt++) {
                int row = wr * 64 + mt * 16 + g;
                a_hi[mt][0] = *(const uint32_t*)&sAh[row * SSTR32 + kb];
                a_hi[mt][1] = *(const uint32_t*)&sAh[(row + 8) * SSTR32 + kb];
                a_hi[mt][2] = *(const uint32_t*)&sAh[row * SSTR32 + kb + 8];
                a_hi[mt][3] = *(const uint32_t*)&sAh[(row + 8) * SSTR32 + kb + 8];
                a_lo[mt][0] = *(const uint32_t*)&sAl[row * SSTR32 + kb];
                a_lo[mt][1] = *(const uint32_t*)&sAl[(row + 8) * SSTR32 + kb];
                a_lo[mt][2] = *(const uint32_t*)&sAl[row * SSTR32 + kb + 8];
                a_lo[mt][3] = *(const uint32_t*)&sAl[(row + 8) * SSTR32 + kb + 8];
            }
            #pragma unroll
            for (int nt = 0; nt < 4; nt++) {
                int rn = wc * 32 + nt * 8 + g;
                b_hi[nt][0] = *(const uint32_t*)&sBh[rn * SSTR32 + kb];
                b_hi[nt][1] = *(const uint32_t*)&sBh[rn * SSTR32 + kb + 8];
                b_lo[nt][0] = *(const uint32_t*)&sBl[rn * SSTR32 + kb];
                b_lo[nt][1] = *(const uint32_t*)&sBl[rn * SSTR32 + kb + 8];
            }
            #pragma unroll
            for (int mt = 0; mt < 4; mt++)
                #pragma unroll
                for (int nt = 0; nt < 4; nt++) {
                    mma16816(acc[mt][nt], a_hi[mt], b_hi[nt]);
                    mma16816(acc[mt][nt], a_hi[mt], b_lo[nt]);
                    mma16816(acc[mt][nt], a_lo[mt], b_hi[nt]);
                }
        }
        __syncthreads();
    }
    gemm_epilogue(acc, Cout, ldc, m0, n0, wr, wc, g, tg);
}

// ---------------- fallback: BK=16, static smem (proven R7 kernel) ----------------
#define SSTR 24
#define TILE_E (128 * SSTR)
#define STAGE_E (4 * TILE_E)
__global__ void __launch_bounds__(256, 2) k_mma_gemm16(int mode) {
    __shared__ __align__(16) __nv_bfloat16 smem[2 * STAGE_E];   // 49152 bytes

    const __nv_bfloat16 *Ah, *Al, *Bh, *Bl;
    float* Cout; int K, ldc;
    gemm_cfg(mode, Ah, Al, Bh, Bl, Cout, K, ldc);

    int tid = threadIdx.x, warp = tid >> 5, lane = tid & 31;
    int wr = warp >> 2, wc = warp & 3;
    int g = lane >> 2, tg = lane & 3;
    int m0 = blockIdx.y * 128, n0 = blockIdx.x * 128;

    const __nv_bfloat16* base0 = Ah + (size_t)m0 * K;
    const __nv_bfloat16* base1 = Al + (size_t)m0 * K;
    const __nv_bfloat16* base2 = Bh + (size_t)n0 * K;
    const __nv_bfloat16* base3 = Bl + (size_t)n0 * K;

    uint32_t sbase = (uint32_t)__cvta_generic_to_shared(smem);
    int lr = tid >> 1, lq = tid & 1;
    size_t goff = (size_t)lr * K + lq * 8;
    uint32_t soff = (uint32_t)(lr * SSTR + lq * 8) * 2;

    float acc[4][4][4];
    #pragma unroll
    for (int i = 0; i < 4; i++)
        #pragma unroll
        for (int j = 0; j < 4; j++)
            #pragma unroll
            for (int q = 0; q < 4; q++) acc[i][j][q] = 0.f;

    {
        uint32_t sb = sbase + soff;
        cp16(sb + 0 * TILE_E * 2, base0 + goff);
        cp16(sb + 1 * TILE_E * 2, base1 + goff);
        cp16(sb + 2 * TILE_E * 2, base2 + goff);
        cp16(sb + 3 * TILE_E * 2, base3 + goff);
        CP_COMMIT();
    }

    const int T = K >> 4;
    for (int it = 0; it < T; it++) {
        if (it + 1 < T) {
            int k0n = (it + 1) << 4;
            uint32_t sb = sbase + ((it + 1) & 1) * STAGE_E * 2 + soff;
            cp16(sb + 0 * TILE_E * 2, base0 + goff + k0n);
            cp16(sb + 1 * TILE_E * 2, base1 + goff + k0n);
            cp16(sb + 2 * TILE_E * 2, base2 + goff + k0n);
            cp16(sb + 3 * TILE_E * 2, base3 + goff + k0n);
            CP_COMMIT();
            CP_WAIT(1);
        } else {
            CP_WAIT(0);
        }
        __syncthreads();

        const __nv_bfloat16* s0 = smem + (it & 1) * STAGE_E;
        const __nv_bfloat16* sAh = s0;
        const __nv_bfloat16* sAl = s0 + TILE_E;
        const __nv_bfloat16* sBh = s0 + 2 * TILE_E;
        const __nv_bfloat16* sBl = s0 + 3 * TILE_E;
        int kb = tg * 2;

        uint32_t a_hi[4][4], a_lo[4][4], b_hi[4][2], b_lo[4][2];
        #pragma unroll
        for (int mt = 0; mt < 4; mt++) {
            int row = wr * 64 + mt * 16 + g;
            a_hi[mt][0] = *(const uint32_t*)&sAh[row * SSTR + kb];
            a_hi[mt][1] = *(const uint32_t*)&sAh[(row + 8) * SSTR + kb];
            a_hi[mt][2] = *(const uint32_t*)&sAh[row * SSTR + kb + 8];
            a_hi[mt][3] = *(const uint32_t*)&sAh[(row + 8) * SSTR + kb + 8];
            a_lo[mt][0] = *(const uint32_t*)&sAl[row * SSTR + kb];
            a_lo[mt][1] = *(const uint32_t*)&sAl[(row + 8) * SSTR + kb];
            a_lo[mt][2] = *(const uint32_t*)&sAl[row * SSTR + kb + 8];
            a_lo[mt][3] = *(const uint32_t*)&sAl[(row + 8) * SSTR + kb + 8];
        }
        #pragma unroll
        for (int nt = 0; nt < 4; nt++) {
            int rn = wc * 32 + nt * 8 + g;
            b_hi[nt][0] = *(const uint32_t*)&sBh[rn * SSTR + kb];
            b_hi[nt][1] = *(const uint32_t*)&sBh[rn * SSTR + kb + 8];
            b_lo[nt][0] = *(const uint32_t*)&sBl[rn * SSTR + kb];
            b_lo[nt][1] = *(const uint32_t*)&sBl[rn * SSTR + kb + 8];
        }
        #pragma unroll
        for (int mt = 0; mt < 4; mt++)
            #pragma unroll
            for (int nt = 0; nt < 4; nt++) {
                mma16816(acc[mt][nt], a_hi[mt], b_hi[nt]);
                mma16816(acc[mt][nt], a_hi[mt], b_lo[nt]);
                mma16816(acc[mt][nt], a_lo[mt], b_hi[nt]);
            }
        __syncthreads();
    }
    gemm_epilogue(acc, Cout, ldc, m0, n0, wr, wc, g, tg);
}

// ---------------- depthwise conv(4, causal) + bias + silu ----------------
__global__ void k_conv_silu(const float* __restrict__ cw, const float* __restrict__ cb) {
    int s = blockIdx.x;
    int d = blockIdx.y * 128 + threadIdx.x;
    float w0 = cw[d * 4 + 0], w1 = cw[d * 4 + 1], w2 = cw[d * 4 + 2], w3 = cw[d * 4 + 3];
    float bias = cb[d];
    float x0 = 0.f, x1 = 0.f, x2 = 0.f;
    const float* xp = g_xz + (size_t)s * LSEQ * NXZ + d;
    float*       op = g_xc + (size_t)s * LSEQ * DI  + d;
    #pragma unroll 4
    for (int t = 0; t < LSEQ; t++) {
        float x3 = xp[t * NXZ];
        float a = fmaf(w3, x3, fmaf(w2, x2, fmaf(w1, x1, fmaf(w0, x0, bias))));
        op[t * DI] = siluf(a);
        x0 = x1; x1 = x2; x2 = x3;
    }
}

// ---------------- x-proj GEMM: g_dbc[m, 0:48] = g_xc[m,:] @ W_xproj ----------------
__global__ void __launch_bounds__(256) k_xproj(const float* __restrict__ Wx) {
    __shared__ float As[32][65];
    __shared__ float Bs[32][48];
    int m0 = blockIdx.x * 64;
    int tid = threadIdx.x;
    int row = tid & 63;
    int cg  = tid >> 6;
    float acc[12];
    #pragma unroll
    for (int j = 0; j < 12; j++) acc[j] = 0.f;

    for (int k0 = 0; k0 < DI; k0 += 32) {
        #pragma unroll
        for (int i = 0; i < 8; i++) {
            int idx = tid + i * 256;
            int r = idx >> 5, k = idx & 31;
            As[k][r] = g_xc[(size_t)(m0 + r) * DI + k0 + k];
        }
        #pragma unroll
        for (int i = 0; i < 6; i++) {
            int idx = tid + i * 256;
            int k = idx / 48, n = idx % 48;
            Bs[k][n] = Wx[(k0 + k) * NXP + n];
        }
        __syncthreads();
        #pragma unroll
        for (int k = 0; k < 32; k++) {
            float a = As[k][row];
            #pragma unroll
            for (int j = 0; j < 12; j++) acc[j] = fmaf(a, Bs[k][cg * 12 + j], acc[j]);
        }
        __syncthreads();
    }
    #pragma unroll
    for (int j = 0; j < 12; j++)
        g_dbc[(size_t)(m0 + row) * NXP + cg * 12 + j] = acc[j];
}

// ---------------- selective scan (dt-proj + softplus + gate fused) ----------------
__global__ void __launch_bounds__(512) k_scan(const float* __restrict__ Alog,
                                              const float* __restrict__ Wdt,
                                              const float* __restrict__ bdt,
                                              const float* __restrict__ Dp) {
    __shared__ float Rs[LSEQ][DTR];
    __shared__ float Bs[LSEQ][DST];
    __shared__ float Cs[LSEQ][DST];
    int s = blockIdx.x;
    int d = threadIdx.x;
    for (int i = threadIdx.x; i < LSEQ * NXP; i += 512) {
        int t = i / NXP, j = i % NXP;
        float v = g_dbc[(size_t)(s * LSEQ + t) * NXP + j];
        if (j < DTR) Rs[t][j] = v;
        else if (j < DTR + DST) Bs[t][j - DTR] = v;
        else Cs[t][j - DTR - DST] = v;
    }
    __syncthreads();
    float A[DST], h[DST], w[DTR];
    #pragma unroll
    for (int n = 0; n < DST; n++) { A[n] = -expf(Alog[d * DST + n]); h[n] = 0.f; }
    #pragma unroll
    for (int i = 0; i < DTR; i++) w[i] = Wdt[i * DI + d];
    float bd = bdt[d];
    float Dd = Dp[d];
    const float* xp = g_xc + (size_t)s * LSEQ * DI + d;
    const float* zp = g_xz + (size_t)s * LSEQ * NXZ + DI + d;
    __nv_bfloat16* yhp = g_yh + (size_t)s * LSEQ * DI + d;
    __nv_bfloat16* ylp = g_yl + (size_t)s * LSEQ * DI + d;
    for (int t = 0; t < LSEQ; t++) {
        float acc = bd;
        #pragma unroll
        for (int i = 0; i < DTR; i++) acc = fmaf(Rs[t][i], w[i], acc);
        float dt = softplusf(acc);
        float xc = xp[t * DI];
        float dtx = dt * xc;
        float y = 0.f;
        #pragma unroll
        for (int n = 0; n < DST; n++) {
            float dA = __expf(dt * A[n]);
            h[n] = fmaf(dA, h[n], dtx * Bs[t][n]);
            y = fmaf(h[n], Cs[t][n], y);
        }
        // fused gate: v = (y + xc*D) * silu(z), split to bf16 hi/lo
        float z = zp[t * NXZ];
        float v = fmaf(xc, Dd, y) * siluf(z);
        __nv_bfloat16 hh = __float2bfloat16(v);
        yhp[t * DI] = hh;
        ylp[t * DI] = __float2bfloat16(v - __bfloat162float(hh));
    }
}

// ---------------- scatter g_tmp -> out(b,c,h,w) ----------------
__global__ void k_scatter(float* __restrict__ out, int dir, int accum) {
    __shared__ float tile[32][33];
    int rt = blockIdx.x, ct = blockIdx.y, b = blockIdx.z;
    int tx = threadIdx.x, ty = threadIdx.y;
    int c0 = ct * 32;
    if (dir == 0) {
        int rem0 = rt * 32;
        #pragma unroll
        for (int i = 0; i < 4; i++) {
            int rem = rem0 + ty + i * 8;
            tile[ty + i * 8][tx] = g_tmp[(size_t)(b * 4096 + rem) * CDIM + c0 + tx];
        }
        __syncthreads();
        #pragma unroll
        for (int i = 0; i < 4; i++) {
            int c = c0 + ty + i * 8;
            size_t o = (size_t)(b * 256 + c) * 4096 + rem0 + tx;
            float v = tile[tx][ty + i * 8];
            if (accum) out[o] += v; else out[o] = v;
        }
    } else {
        int h = rt >> 1, w0 = (rt & 1) * 32;
        #pragma unroll
        for (int i = 0; i < 4; i++) {
            int w = w0 + ty + i * 8;
            tile[ty + i * 8][tx] = g_tmp[(size_t)(b * 4096 + w * 64 + h) * CDIM + c0 + tx];
        }
        __syncthreads();
        #pragma unroll
        for (int i = 0; i < 4; i++) {
            int c = c0 + ty + i * 8;
            size_t o = (size_t)(b * 256 + c) * 4096 + h * 64 + w0 + tx;
            float v = tile[tx][ty + i * 8];
            if (accum) out[o] += v; else out[o] = v;
        }
    }
}

// ---------------- launch ----------------
extern "C" void kernel_launch(void* const* d_in, const int* in_sizes, int n_in,
                              void* d_out, int out_size) {
    const float* x = (const float*)d_in[0];
    float* out = (float*)d_out;

    // Prefer BK=32 dynamic-smem GEMM; fall back to static BK=16 if opt-in fails.
    cudaError_t e = cudaFuncSetAttribute(k_mma_gemm32,
        cudaFuncAttributeMaxDynamicSharedMemorySize, 2 * STG32 * 2);
    bool use32 = (e == cudaSuccess);
    cudaGetLastError();   // clear any non-sticky error state

    k_transpose_hw<<<dim3(2, 2, 2048), dim3(32, 8)>>>(x);

    for (int dir = 0; dir < 2; dir++) {
        const float* Win  = (const float*)d_in[1 + dir * 9 + 0];
        const float* cw   = (const float*)d_in[1 + dir * 9 + 1];
        const float* cb   = (const float*)d_in[1 + dir * 9 + 2];
        const float* Wx   = (const float*)d_in[1 + dir * 9 + 3];
        const float* Wdt  = (const float*)d_in[1 + dir * 9 + 4];
        const float* bdt  = (const float*)d_in[1 + dir * 9 + 5];
        const float* Alog = (const float*)d_in[1 + dir * 9 + 6];
        const float* Dp   = (const float*)d_in[1 + dir * 9 + 7];
        const float* Wout = (const float*)d_in[1 + dir * 9 + 8];

        k_convA<<<dim3(128, 8, 8), dim3(32, 8)>>>(x, dir);
        k_convW<<<dim3(1024 / 32, 256 / 32), dim3(32, 8)>>>(Win, 256, 1024, 0);
        if (use32) k_mma_gemm32<<<dim3(8, 256), 256, 2 * STG32 * 2>>>(0);
        else       k_mma_gemm16<<<dim3(8, 256), 256>>>(0);
        k_conv_silu<<<dim3(NSEQ, 4), 128>>>(cw, cb);
        k_xproj<<<MDIM / 64, 256>>>(Wx);
        k_scan<<<NSEQ, 512>>>(Alog, Wdt, bdt, Dp);
        k_convW<<<dim3(256 / 32, 512 / 32), dim3(32, 8)>>>(Wout, 512, 256, 1);
        if (use32) k_mma_gemm32<<<dim3(2, 256), 256, 2 * STG32 * 2>>>(1);
        else       k_mma_gemm16<<<dim3(2, 256), 256>>>(1);
        k_scatter<<<dim3(128, 8, 8), dim3(32, 8)>>>(out, dir, dir);
    }
}

// round 9
// speedup vs baseline: 1.2474x; 1.2474x over previous
#include <cuda_runtime.h>
#include <cuda_bf16.h>
#include <cstdint>
#include <math.h>

// ---------------- problem constants ----------------
#define NSEQ   512
#define LSEQ   64
#define MDIM   (NSEQ*LSEQ)  // 32768
#define CDIM   256
#define DI     512
#define NXZ    1024
#define DST    16
#define DTR    16
#define NXP    48

// ---------------- scratch (device symbols: referenced ONLY inside device code) ----------------
__device__ float g_xz [MDIM * NXZ];     // 134 MB
__device__ float g_xc [MDIM * DI];      // 67 MB
__device__ float g_dbc[MDIM * NXP];     // 6.3 MB
__device__ float g_y  [MDIM * DI];      // 67 MB (scan out)
__device__ float g_tmp[MDIM * CDIM];    // 33.5 MB
__device__ float g_xT [8 * 256 * 64 * 64];
__device__ __nv_bfloat16 g_ah [MDIM * 256];
__device__ __nv_bfloat16 g_al [MDIM * 256];
__device__ __nv_bfloat16 g_yh [MDIM * DI];
__device__ __nv_bfloat16 g_yl [MDIM * DI];
__device__ __nv_bfloat16 g_wtih[1024 * 256];
__device__ __nv_bfloat16 g_wtil[1024 * 256];
__device__ __nv_bfloat16 g_wtoh[256 * 512];
__device__ __nv_bfloat16 g_wtol[256 * 512];

__device__ __forceinline__ float siluf(float v)    { return v / (1.f + __expf(-v)); }
__device__ __forceinline__ float softplusf(float v){ return (v > 20.f) ? v : log1pf(expf(v)); }

// ---------------- mma.sync / cp.async helpers ----------------
__device__ __forceinline__ void mma16816(float* c, const uint32_t* a, const uint32_t* b) {
    asm volatile(
        "mma.sync.aligned.m16n8k16.row.col.f32.bf16.bf16.f32 "
        "{%0,%1,%2,%3}, {%4,%5,%6,%7}, {%8,%9}, {%0,%1,%2,%3};\n"
        : "+f"(c[0]), "+f"(c[1]), "+f"(c[2]), "+f"(c[3])
        : "r"(a[0]), "r"(a[1]), "r"(a[2]), "r"(a[3]), "r"(b[0]), "r"(b[1]));
}
__device__ __forceinline__ void cp16(uint32_t saddr, const void* g) {
    asm volatile("cp.async.cg.shared.global [%0], [%1], 16;" :: "r"(saddr), "l"(g));
}
#define CP_COMMIT() asm volatile("cp.async.commit_group;" ::: "memory")
#define CP_WAIT(n)  asm volatile("cp.async.wait_group %0;" :: "n"(n) : "memory")

// ---------------- transpose x(b,c,h,w) -> xT(b,c,w,h) ----------------
__global__ void k_transpose_hw(const float* __restrict__ x) {
    __shared__ float tile[32][33];
    int bc = blockIdx.z, ht = blockIdx.y, wt = blockIdx.x;
    const float* src = x    + (size_t)bc * 4096;
    float*       dst = g_xT + (size_t)bc * 4096;
    int tx = threadIdx.x, ty = threadIdx.y;
    #pragma unroll
    for (int i = 0; i < 4; i++) {
        int h = ht * 32 + ty + i * 8;
        tile[ty + i * 8][tx] = src[h * 64 + wt * 32 + tx];
    }
    __syncthreads();
    #pragma unroll
    for (int i = 0; i < 4; i++) {
        int w = wt * 32 + ty + i * 8;
        dst[w * 64 + ht * 32 + tx] = tile[tx][ty + i * 8];
    }
}

// ---------------- convert A: src[(b*256+k)*4096+rem] -> bf16 hi/lo [m][k] ----------------
__global__ void k_convA(const float* __restrict__ xin, int useT) {
    __shared__ float t[32][33];
    const float* src = useT ? g_xT : xin;
    int b = blockIdx.z, kt = blockIdx.y, rt = blockIdx.x;
    int tx = threadIdx.x, ty = threadIdx.y;
    #pragma unroll
    for (int i = 0; i < 4; i++) {
        int k = kt * 32 + ty + i * 8;
        t[ty + i * 8][tx] = src[(size_t)(b * 256 + k) * 4096 + rt * 32 + tx];
    }
    __syncthreads();
    #pragma unroll
    for (int i = 0; i < 4; i++) {
        int rem = rt * 32 + ty + i * 8;
        size_t m = (size_t)b * 4096 + rem;
        float v = t[tx][ty + i * 8];
        __nv_bfloat16 h = __float2bfloat16(v);
        g_ah[m * 256 + kt * 32 + tx] = h;
        g_al[m * 256 + kt * 32 + tx] = __float2bfloat16(v - __bfloat162float(h));
    }
}

// ---------------- convert+transpose weights: W[R,C] fp32 -> T[C,R] bf16 hi/lo ----------------
__global__ void k_convW(const float* __restrict__ W, int R, int C, int which) {
    __shared__ float t[32][33];
    __nv_bfloat16* Th = which ? g_wtoh : g_wtih;
    __nv_bfloat16* Tl = which ? g_wtol : g_wtil;
    int r0 = blockIdx.y * 32, c0 = blockIdx.x * 32;
    int tx = threadIdx.x, ty = threadIdx.y;
    #pragma unroll
    for (int i = 0; i < 4; i++)
        t[ty + i * 8][tx] = W[(size_t)(r0 + ty + i * 8) * C + c0 + tx];
    __syncthreads();
    #pragma unroll
    for (int i = 0; i < 4; i++) {
        float v = t[tx][ty + i * 8];
        int oc = c0 + ty + i * 8;
        __nv_bfloat16 h = __float2bfloat16(v);
        Th[(size_t)oc * R + r0 + tx] = h;
        Tl[(size_t)oc * R + r0 + tx] = __float2bfloat16(v - __bfloat162float(h));
    }
}

// ---------------- shared GEMM config ----------------
__device__ __forceinline__ void gemm_cfg(int mode, const __nv_bfloat16*& Ah,
    const __nv_bfloat16*& Al, const __nv_bfloat16*& Bh, const __nv_bfloat16*& Bl,
    float*& Cout, int& K, int& ldc)
{
    if (mode == 0) { Ah = g_ah; Al = g_al; Bh = g_wtih; Bl = g_wtil; Cout = g_xz;  K = 256; ldc = NXZ; }
    else           { Ah = g_yh; Al = g_yl; Bh = g_wtoh; Bl = g_wtol; Cout = g_tmp; K = 512; ldc = CDIM; }
}

__device__ __forceinline__ void gemm_epilogue(float acc[4][4][4], float* Cout, int ldc,
                                              int m0, int n0, int wr, int wc, int g, int tg)
{
    #pragma unroll
    for (int mt = 0; mt < 4; mt++)
        #pragma unroll
        for (int nt = 0; nt < 4; nt++) {
            int row = m0 + wr * 64 + mt * 16 + g;
            int col = n0 + wc * 32 + nt * 8 + tg * 2;
            *(float2*)&Cout[(size_t)row * ldc + col] =
                make_float2(acc[mt][nt][0], acc[mt][nt][1]);
            *(float2*)&Cout[(size_t)(row + 8) * ldc + col] =
                make_float2(acc[mt][nt][2], acc[mt][nt][3]);
        }
}

// ---------------- HMMA bf16x3 GEMM, BK=32, cp.async 2-stage, DYNAMIC smem ----------------
#define SSTR32 40
#define TILE32 (128 * SSTR32)
#define STG32  (4 * TILE32)
__global__ void __launch_bounds__(256, 2) k_mma_gemm32(int mode) {
    extern __shared__ __nv_bfloat16 dsm[];

    const __nv_bfloat16 *Ah, *Al, *Bh, *Bl;
    float* Cout; int K, ldc;
    gemm_cfg(mode, Ah, Al, Bh, Bl, Cout, K, ldc);

    int tid = threadIdx.x, warp = tid >> 5, lane = tid & 31;
    int wr = warp >> 2, wc = warp & 3;
    int g = lane >> 2, tg = lane & 3;
    int m0 = blockIdx.y * 128, n0 = blockIdx.x * 128;

    const __nv_bfloat16* base0 = Ah + (size_t)m0 * K;
    const __nv_bfloat16* base1 = Al + (size_t)m0 * K;
    const __nv_bfloat16* base2 = Bh + (size_t)n0 * K;
    const __nv_bfloat16* base3 = Bl + (size_t)n0 * K;

    uint32_t sbase = (uint32_t)__cvta_generic_to_shared(dsm);
    float acc[4][4][4];
    #pragma unroll
    for (int i = 0; i < 4; i++)
        #pragma unroll
        for (int j = 0; j < 4; j++)
            #pragma unroll
            for (int q = 0; q < 4; q++) acc[i][j][q] = 0.f;

    #pragma unroll
    for (int i = 0; i < 2; i++) {
        int idx = tid + i * 256;
        int r = idx >> 2, q = idx & 3;
        size_t go = (size_t)r * K + q * 8;
        uint32_t so = sbase + (uint32_t)(r * SSTR32 + q * 8) * 2;
        cp16(so + 0 * TILE32 * 2, base0 + go);
        cp16(so + 1 * TILE32 * 2, base1 + go);
        cp16(so + 2 * TILE32 * 2, base2 + go);
        cp16(so + 3 * TILE32 * 2, base3 + go);
    }
    CP_COMMIT();

    const int T = K >> 5;
    for (int it = 0; it < T; it++) {
        if (it + 1 < T) {
            int k0n = (it + 1) << 5;
            uint32_t sb = sbase + ((it + 1) & 1) * STG32 * 2;
            #pragma unroll
            for (int i = 0; i < 2; i++) {
                int idx = tid + i * 256;
                int r = idx >> 2, q = idx & 3;
                size_t go = (size_t)r * K + q * 8 + k0n;
                uint32_t so = sb + (uint32_t)(r * SSTR32 + q * 8) * 2;
                cp16(so + 0 * TILE32 * 2, base0 + go);
                cp16(so + 1 * TILE32 * 2, base1 + go);
                cp16(so + 2 * TILE32 * 2, base2 + go);
                cp16(so + 3 * TILE32 * 2, base3 + go);
            }
            CP_COMMIT();
            CP_WAIT(1);
        } else {
            CP_WAIT(0);
        }
        __syncthreads();

        const __nv_bfloat16* s0  = dsm + (it & 1) * STG32;
        const __nv_bfloat16* sAh = s0;
        const __nv_bfloat16* sAl = s0 + TILE32;
        const __nv_bfloat16* sBh = s0 + 2 * TILE32;
        const __nv_bfloat16* sBl = s0 + 3 * TILE32;

        #pragma unroll
        for (int ks = 0; ks < 2; ks++) {
            int kb = ks * 16 + tg * 2;
            uint32_t a_hi[4][4], a_lo[4][4], b_hi[4][2], b_lo[4][2];
            #pragma unroll
            for (int mt = 0; mt < 4; mt++) {
                int row = wr * 64 + mt * 16 + g;
                a_hi[mt][0] = *(const uint32_t*)&sAh[row * SSTR32 + kb];
                a_hi[mt][1] = *(const uint32_t*)&sAh[(row + 8) * SSTR32 + kb];
                a_hi[mt][2] = *(const uint32_t*)&sAh[row * SSTR32 + kb + 8];
                a_hi[mt][3] = *(const uint32_t*)&sAh[(row + 8) * SSTR32 + kb + 8];
                a_lo[mt][0] = *(const uint32_t*)&sAl[row * SSTR32 + kb];
                a_lo[mt][1] = *(const uint32_t*)&sAl[(row + 8) * SSTR32 + kb];
                a_lo[mt][2] = *(const uint32_t*)&sAl[row * SSTR32 + kb + 8];
                a_lo[mt][3] = *(const uint32_t*)&sAl[(row + 8) * SSTR32 + kb + 8];
            }
            #pragma unroll
            for (int nt = 0; nt < 4; nt++) {
                int rn = wc * 32 + nt * 8 + g;
                b_hi[nt][0] = *(const uint32_t*)&sBh[rn * SSTR32 + kb];
                b_hi[nt][1] = *(const uint32_t*)&sBh[rn * SSTR32 + kb + 8];
                b_lo[nt][0] = *(const uint32_t*)&sBl[rn * SSTR32 + kb];
                b_lo[nt][1] = *(const uint32_t*)&sBl[rn * SSTR32 + kb + 8];
            }
            #pragma unroll
            for (int mt = 0; mt < 4; mt++)
                #pragma unroll
                for (int nt = 0; nt < 4; nt++) {
                    mma16816(acc[mt][nt], a_hi[mt], b_hi[nt]);
                    mma16816(acc[mt][nt], a_hi[mt], b_lo[nt]);
                    mma16816(acc[mt][nt], a_lo[mt], b_hi[nt]);
                }
        }
        __syncthreads();
    }
    gemm_epilogue(acc, Cout, ldc, m0, n0, wr, wc, g, tg);
}

// ---------------- fallback: BK=16, static smem ----------------
#define SSTR 24
#define TILE_E (128 * SSTR)
#define STAGE_E (4 * TILE_E)
__global__ void __launch_bounds__(256, 2) k_mma_gemm16(int mode) {
    __shared__ __align__(16) __nv_bfloat16 smem[2 * STAGE_E];

    const __nv_bfloat16 *Ah, *Al, *Bh, *Bl;
    float* Cout; int K, ldc;
    gemm_cfg(mode, Ah, Al, Bh, Bl, Cout, K, ldc);

    int tid = threadIdx.x, warp = tid >> 5, lane = tid & 31;
    int wr = warp >> 2, wc = warp & 3;
    int g = lane >> 2, tg = lane & 3;
    int m0 = blockIdx.y * 128, n0 = blockIdx.x * 128;

    const __nv_bfloat16* base0 = Ah + (size_t)m0 * K;
    const __nv_bfloat16* base1 = Al + (size_t)m0 * K;
    const __nv_bfloat16* base2 = Bh + (size_t)n0 * K;
    const __nv_bfloat16* base3 = Bl + (size_t)n0 * K;

    uint32_t sbase = (uint32_t)__cvta_generic_to_shared(smem);
    int lr = tid >> 1, lq = tid & 1;
    size_t goff = (size_t)lr * K + lq * 8;
    uint32_t soff = (uint32_t)(lr * SSTR + lq * 8) * 2;

    float acc[4][4][4];
    #pragma unroll
    for (int i = 0; i < 4; i++)
        #pragma unroll
        for (int j = 0; j < 4; j++)
            #pragma unroll
            for (int q = 0; q < 4; q++) acc[i][j][q] = 0.f;

    {
        uint32_t sb = sbase + soff;
        cp16(sb + 0 * TILE_E * 2, base0 + goff);
        cp16(sb + 1 * TILE_E * 2, base1 + goff);
        cp16(sb + 2 * TILE_E * 2, base2 + goff);
        cp16(sb + 3 * TILE_E * 2, base3 + goff);
        CP_COMMIT();
    }

    const int T = K >> 4;
    for (int it = 0; it < T; it++) {
        if (it + 1 < T) {
            int k0n = (it + 1) << 4;
            uint32_t sb = sbase + ((it + 1) & 1) * STAGE_E * 2 + soff;
            cp16(sb + 0 * TILE_E * 2, base0 + goff + k0n);
            cp16(sb + 1 * TILE_E * 2, base1 + goff + k0n);
            cp16(sb + 2 * TILE_E * 2, base2 + goff + k0n);
            cp16(sb + 3 * TILE_E * 2, base3 + goff + k0n);
            CP_COMMIT();
            CP_WAIT(1);
        } else {
            CP_WAIT(0);
        }
        __syncthreads();

        const __nv_bfloat16* s0 = smem + (it & 1) * STAGE_E;
        const __nv_bfloat16* sAh = s0;
        const __nv_bfloat16* sAl = s0 + TILE_E;
        const __nv_bfloat16* sBh = s0 + 2 * TILE_E;
        const __nv_bfloat16* sBl = s0 + 3 * TILE_E;
        int kb = tg * 2;

        uint32_t a_hi[4][4], a_lo[4][4], b_hi[4][2], b_lo[4][2];
        #pragma unroll
        for (int mt = 0; mt < 4; mt++) {
            int row = wr * 64 + mt * 16 + g;
            a_hi[mt][0] = *(const uint32_t*)&sAh[row * SSTR + kb];
            a_hi[mt][1] = *(const uint32_t*)&sAh[(row + 8) * SSTR + kb];
            a_hi[mt][2] = *(const uint32_t*)&sAh[row * SSTR + kb + 8];
            a_hi[mt][3] = *(const uint32_t*)&sAh[(row + 8) * SSTR + kb + 8];
            a_lo[mt][0] = *(const uint32_t*)&sAl[row * SSTR + kb];
            a_lo[mt][1] = *(const uint32_t*)&sAl[(row + 8) * SSTR + kb];
            a_lo[mt][2] = *(const uint32_t*)&sAl[row * SSTR + kb + 8];
            a_lo[mt][3] = *(const uint32_t*)&sAl[(row + 8) * SSTR + kb + 8];
        }
        #pragma unroll
        for (int nt = 0; nt < 4; nt++) {
            int rn = wc * 32 + nt * 8 + g;
            b_hi[nt][0] = *(const uint32_t*)&sBh[rn * SSTR + kb];
            b_hi[nt][1] = *(const uint32_t*)&sBh[rn * SSTR + kb + 8];
            b_lo[nt][0] = *(const uint32_t*)&sBl[rn * SSTR + kb];
            b_lo[nt][1] = *(const uint32_t*)&sBl[rn * SSTR + kb + 8];
        }
        #pragma unroll
        for (int mt = 0; mt < 4; mt++)
            #pragma unroll
            for (int nt = 0; nt < 4; nt++) {
                mma16816(acc[mt][nt], a_hi[mt], b_hi[nt]);
                mma16816(acc[mt][nt], a_hi[mt], b_lo[nt]);
                mma16816(acc[mt][nt], a_lo[mt], b_hi[nt]);
            }
        __syncthreads();
    }
    gemm_epilogue(acc, Cout, ldc, m0, n0, wr, wc, g, tg);
}

// ---------------- depthwise conv(4, causal) + bias + silu ----------------
__global__ void k_conv_silu(const float* __restrict__ cw, const float* __restrict__ cb) {
    int s = blockIdx.x;
    int d = blockIdx.y * 128 + threadIdx.x;
    float w0 = cw[d * 4 + 0], w1 = cw[d * 4 + 1], w2 = cw[d * 4 + 2], w3 = cw[d * 4 + 3];
    float bias = cb[d];
    float x0 = 0.f, x1 = 0.f, x2 = 0.f;
    const float* xp = g_xz + (size_t)s * LSEQ * NXZ + d;
    float*       op = g_xc + (size_t)s * LSEQ * DI  + d;
    #pragma unroll 4
    for (int t = 0; t < LSEQ; t++) {
        float x3 = xp[t * NXZ];
        float a = fmaf(w3, x3, fmaf(w2, x2, fmaf(w1, x1, fmaf(w0, x0, bias))));
        op[t * DI] = siluf(a);
        x0 = x1; x1 = x2; x2 = x3;
    }
}

// ---------------- x-proj GEMM: g_dbc[m, 0:48] = g_xc[m,:] @ W_xproj ----------------
__global__ void __launch_bounds__(256) k_xproj(const float* __restrict__ Wx) {
    __shared__ float As[32][65];
    __shared__ float Bs[32][48];
    int m0 = blockIdx.x * 64;
    int tid = threadIdx.x;
    int row = tid & 63;
    int cg  = tid >> 6;
    float acc[12];
    #pragma unroll
    for (int j = 0; j < 12; j++) acc[j] = 0.f;

    for (int k0 = 0; k0 < DI; k0 += 32) {
        #pragma unroll
        for (int i = 0; i < 8; i++) {
            int idx = tid + i * 256;
            int r = idx >> 5, k = idx & 31;
            As[k][r] = g_xc[(size_t)(m0 + r) * DI + k0 + k];
        }
        #pragma unroll
        for (int i = 0; i < 6; i++) {
            int idx = tid + i * 256;
            int k = idx / 48, n = idx % 48;
            Bs[k][n] = Wx[(k0 + k) * NXP + n];
        }
        __syncthreads();
        #pragma unroll
        for (int k = 0; k < 32; k++) {
            float a = As[k][row];
            #pragma unroll
            for (int j = 0; j < 12; j++) acc[j] = fmaf(a, Bs[k][cg * 12 + j], acc[j]);
        }
        __syncthreads();
    }
    #pragma unroll
    for (int j = 0; j < 12; j++)
        g_dbc[(size_t)(m0 + row) * NXP + cg * 12 + j] = acc[j];
}

// ---------------- selective scan (dt-proj fused; exp-recurrence fast path) ----------------
__global__ void __launch_bounds__(512) k_scan(const float* __restrict__ Alog,
                                              const float* __restrict__ Wdt,
                                              const float* __restrict__ bdt) {
    __shared__ float Rs[LSEQ][DTR];
    __shared__ float Bs[LSEQ][DST];
    __shared__ float Cs[LSEQ][DST];
    int s = blockIdx.x;
    int d = threadIdx.x;
    for (int i = threadIdx.x; i < LSEQ * NXP; i += 512) {
        int t = i / NXP, j = i % NXP;
        float v = g_dbc[(size_t)(s * LSEQ + t) * NXP + j];
        if (j < DTR) Rs[t][j] = v;
        else if (j < DTR + DST) Bs[t][j - DTR] = v;
        else Cs[t][j - DTR - DST] = v;
    }
    __syncthreads();
    float A[DST], h[DST], w[DTR];
    bool fast = true;
    #pragma unroll
    for (int n = 0; n < DST; n++) {
        A[n] = -expf(Alog[d * DST + n]);
        h[n] = 0.f;
        fast = fast && (fabsf(A[n] + (float)(n + 1)) <= 1e-3f * (float)(n + 1));
    }
    #pragma unroll
    for (int i = 0; i < DTR; i++) w[i] = Wdt[i * DI + d];
    float bd = bdt[d];
    const float* xp = g_xc + (size_t)s * LSEQ * DI + d;
    float*       yp = g_y  + (size_t)s * LSEQ * DI + d;

    if (fast) {
        // A[n] == -(n+1): exp(dt*A[n]) = r^(n+1), r = exp(-dt). 1 MUFU/step.
        for (int t = 0; t < LSEQ; t++) {
            float acc = bd;
            #pragma unroll
            for (int i = 0; i < DTR; i++) acc = fmaf(Rs[t][i], w[i], acc);
            float dt = softplusf(acc);
            float dtx = dt * xp[t * DI];
            float r = __expf(-dt);
            float y = 0.f, p = 1.f;
            #pragma unroll
            for (int n = 0; n < DST; n++) {
                p *= r;
                h[n] = fmaf(p, h[n], dtx * Bs[t][n]);
                y = fmaf(h[n], Cs[t][n], y);
            }
            yp[t * DI] = y;
        }
    } else {
        for (int t = 0; t < LSEQ; t++) {
            float acc = bd;
            #pragma unroll
            for (int i = 0; i < DTR; i++) acc = fmaf(Rs[t][i], w[i], acc);
            float dt = softplusf(acc);
            float dtx = dt * xp[t * DI];
            float y = 0.f;
            #pragma unroll
            for (int n = 0; n < DST; n++) {
                float dA = __expf(dt * A[n]);
                h[n] = fmaf(dA, h[n], dtx * Bs[t][n]);
                y = fmaf(h[n], Cs[t][n], y);
            }
            yp[t * DI] = y;
        }
    }
}

// ---------------- gate: yb16 = (y + xc*D) * silu(z), split to bf16 hi/lo ----------------
__global__ void k_gate(const float* __restrict__ Dp) {
    size_t i = (size_t)blockIdx.x * 256 + threadIdx.x;
    int d = (int)(i & (DI - 1));
    size_t m = i >> 9;
    float z = g_xz[m * NXZ + DI + d];
    float v = fmaf(g_xc[i], Dp[d], g_y[i]) * siluf(z);
    __nv_bfloat16 h = __float2bfloat16(v);
    g_yh[i] = h;
    g_yl[i] = __float2bfloat16(v - __bfloat162float(h));
}

// ---------------- scatter g_tmp -> out(b,c,h,w) ----------------
__global__ void k_scatter(float* __restrict__ out, int dir, int accum) {
    __shared__ float tile[32][33];
    int rt = blockIdx.x, ct = blockIdx.y, b = blockIdx.z;
    int tx = threadIdx.x, ty = threadIdx.y;
    int c0 = ct * 32;
    if (dir == 0) {
        int rem0 = rt * 32;
        #pragma unroll
        for (int i = 0; i < 4; i++) {
            int rem = rem0 + ty + i * 8;
            tile[ty + i * 8][tx] = g_tmp[(size_t)(b * 4096 + rem) * CDIM + c0 + tx];
        }
        __syncthreads();
        #pragma unroll
        for (int i = 0; i < 4; i++) {
            int c = c0 + ty + i * 8;
            size_t o = (size_t)(b * 256 + c) * 4096 + rem0 + tx;
            float v = tile[tx][ty + i * 8];
            if (accum) out[o] += v; else out[o] = v;
        }
    } else {
        int h = rt >> 1, w0 = (rt & 1) * 32;
        #pragma unroll
        for (int i = 0; i < 4; i++) {
            int w = w0 + ty + i * 8;
            tile[ty + i * 8][tx] = g_tmp[(size_t)(b * 4096 + w * 64 + h) * CDIM + c0 + tx];
        }
        __syncthreads();
        #pragma unroll
        for (int i = 0; i < 4; i++) {
            int c = c0 + ty + i * 8;
            size_t o = (size_t)(b * 256 + c) * 4096 + h * 64 + w0 + tx;
            float v = tile[tx][ty + i * 8];
            if (accum) out[o] += v; else out[o] = v;
        }
    }
}

// ---------------- launch ----------------
extern "C" void kernel_launch(void* const* d_in, const int* in_sizes, int n_in,
                              void* d_out, int out_size) {
    const float* x = (const float*)d_in[0];
    float* out = (float*)d_out;

    cudaError_t e = cudaFuncSetAttribute(k_mma_gemm32,
        cudaFuncAttributeMaxDynamicSharedMemorySize, 2 * STG32 * 2);
    bool use32 = (e == cudaSuccess);
    cudaGetLastError();

    k_transpose_hw<<<dim3(2, 2, 2048), dim3(32, 8)>>>(x);

    for (int dir = 0; dir < 2; dir++) {
        const float* Win  = (const float*)d_in[1 + dir * 9 + 0];
        const float* cw   = (const float*)d_in[1 + dir * 9 + 1];
        const float* cb   = (const float*)d_in[1 + dir * 9 + 2];
        const float* Wx   = (const float*)d_in[1 + dir * 9 + 3];
        const float* Wdt  = (const float*)d_in[1 + dir * 9 + 4];
        const float* bdt  = (const float*)d_in[1 + dir * 9 + 5];
        const float* Alog = (const float*)d_in[1 + dir * 9 + 6];
        const float* Dp   = (const float*)d_in[1 + dir * 9 + 7];
        const float* Wout = (const float*)d_in[1 + dir * 9 + 8];

        k_convA<<<dim3(128, 8, 8), dim3(32, 8)>>>(x, dir);
        k_convW<<<dim3(1024 / 32, 256 / 32), dim3(32, 8)>>>(Win, 256, 1024, 0);
        if (use32) k_mma_gemm32<<<dim3(8, 256), 256, 2 * STG32 * 2>>>(0);
        else       k_mma_gemm16<<<dim3(8, 256), 256>>>(0);
        k_conv_silu<<<dim3(NSEQ, 4), 128>>>(cw, cb);
        k_xproj<<<MDIM / 64, 256>>>(Wx);
        k_scan<<<NSEQ, 512>>>(Alog, Wdt, bdt);
        k_gate<<<(MDIM * DI) / 256, 256>>>(Dp);
        k_convW<<<dim3(256 / 32, 512 / 32), dim3(32, 8)>>>(Wout, 512, 256, 1);
        if (use32) k_mma_gemm32<<<dim3(2, 256), 256, 2 * STG32 * 2>>>(1);
        else       k_mma_gemm16<<<dim3(2, 256), 256>>>(1);
        k_scatter<<<dim3(128, 8, 8), dim3(32, 8)>>>(out, dir, dir);
    }
}